// round 7
// baseline (speedup 1.0000x reference)
#include <cuda_runtime.h>
#include <cstdint>

using ull = unsigned long long;

// ---------- packed f32x2 helpers (Blackwell sm_100a) ----------
__device__ __forceinline__ ull f2pack(float a, float b) {
    ull r; asm("mov.b64 %0, {%1, %2};" : "=l"(r) : "f"(a), "f"(b)); return r;
}
__device__ __forceinline__ void f2unpack(ull p, float& a, float& b) {
    asm("mov.b64 {%0, %1}, %2;" : "=f"(a), "=f"(b) : "l"(p));
}
__device__ __forceinline__ ull f2fma(ull a, ull b, ull c) {
    ull d; asm("fma.rn.f32x2 %0, %1, %2, %3;" : "=l"(d) : "l"(a), "l"(b), "l"(c)); return d;
}
__device__ __forceinline__ ull f2add(ull a, ull b) {
    ull d; asm("add.rn.f32x2 %0, %1, %2;" : "=l"(d) : "l"(a), "l"(b)); return d;
}
__device__ __forceinline__ ull f2mul(ull a, ull b) {
    ull d; asm("mul.rn.f32x2 %0, %1, %2;" : "=l"(d) : "l"(a), "l"(b)); return d;
}
__device__ __forceinline__ ull f2relu(ull p) {
    float a, b; f2unpack(p, a, b);
    return f2pack(fmaxf(a, 0.0f), fmaxf(b, 0.0f));
}
__device__ __forceinline__ ull f2splat(float x) { return f2pack(x, x); }
__device__ __forceinline__ float sigm(float x) { return 1.0f / (1.0f + __expf(-x)); }

// v exchange (ull units): addr = g*SG + i*SI + o.
// SG=180: 2*SG mod 32 = 8 -> per-warp g bases hit distinct bank quads (v LDS128 reads 1 wf).
// SI=22:  2*SI mod 32 = 12 -> 8 i-slots distinct quads (rel LDS128 reads 1 wf). Both 16B-aligned.
#define SG 180
#define SI 22

__global__ __launch_bounds__(128, 4)
void frap_kernel(const float* __restrict__ states,
                 const int*   __restrict__ comp_mask,
                 const int*   __restrict__ phase_pairs,
                 const float* __restrict__ p_w,
                 const float* __restrict__ d_w,  const float* __restrict__ d_b,
                 const float* __restrict__ le_w, const float* __restrict__ le_b,
                 const float* __restrict__ lc_w, const float* __restrict__ lc_b,
                 const float* __restrict__ rel_w,
                 const float* __restrict__ rc_w, const float* __restrict__ rc_b,
                 const float* __restrict__ h_w,  const float* __restrict__ h_b,
                 const float* __restrict__ bm_w, const float* __restrict__ bm_b,
                 float* __restrict__ out, int B)
{
    // all weights pre-splatted (w,w) -> one LDS128 feeds 2 FFMA2
    __shared__ __align__(16) ull s_lcA[20][16];
    __shared__ __align__(16) ull s_lcB[20][16];
    __shared__ __align__(16) ull s_hw[20][20];
    __shared__ __align__(16) ull s_rel[8 * 8 * SI];  // [q][i] slot stride SI; zero row q==i
    __shared__ __align__(16) ull s_leD[4][16];
    __shared__ ull  s_dw[4], s_db[4], s_lcb[20], s_hb[20], s_bmw[20];
    __shared__ float s_base[2][16];
    __shared__ int   s_pp[16];
    __shared__ float s_bmb, s_corr;
    __shared__ __align__(16) ull s_v[16 * SG];       // per batch-PAIR g: v[8][20] packed

    const int tid = threadIdx.x;

    // ---------------- block-local precompute ----------------
    for (int idx = tid; idx < 320; idx += 128) {
        int o = idx >> 4, c = idx & 15;
        s_lcA[o][c] = f2splat(lc_w[o * 32 + c]);
        s_lcB[o][c] = f2splat(lc_w[o * 32 + 16 + c]);
    }
    for (int idx = tid; idx < 400; idx += 128) {
        int o = idx / 20, c = idx % 20;
        s_hw[o][c] = f2splat(h_w[o * 20 + c]);
    }
    // s_rel[q][i][o]: rel row for pair (i, j=q); zero when q==i (dummy lane, corrected)
    for (int idx = tid; idx < 1280; idx += 128) {
        int qi = idx / 20, o = idx % 20;
        int q = qi >> 3, i = qi & 7;
        float val = 0.0f;
        if (q != i) {
            int cm = i * 7 + (q > i ? q - 1 : q);
            int e = comp_mask[cm];
            float acc = rc_b[o];
            #pragma unroll
            for (int c4 = 0; c4 < 4; c4++)
                acc += fmaxf(rel_w[e * 4 + c4], 0.0f) * rc_w[o * 4 + c4];
            val = fmaxf(acc, 0.0f);
        }
        s_rel[qi * SI + o - (qi * 20) + qi * 20] = 0;  // placeholder (overwritten below)
        s_rel[qi * SI + o] = f2splat(val);
    }
    for (int idx = tid; idx < 64; idx += 128) {
        int k = idx >> 4, c = idx & 15;
        s_leD[k][c] = f2splat(le_w[(4 + k) * 16 + c]);
    }
    if (tid < 32) {
        int e = tid >> 4, c = tid & 15;
        float a = le_b[c];
        #pragma unroll
        for (int k = 0; k < 4; k++) a += sigm(p_w[e * 4 + k]) * le_w[k * 16 + c];
        s_base[e][c] = a;
    }
    if (tid < 20) {
        s_lcb[tid] = f2splat(lc_b[tid]);
        s_hb[tid]  = f2splat(h_b[tid]);
        s_bmw[tid] = f2splat(bm_w[tid]);
    }
    if (tid < 4) { s_dw[tid] = f2splat(d_w[tid]); s_db[tid] = f2splat(d_b[tid]); }
    if (tid < 16) s_pp[tid] = phase_pairs[tid];
    if (tid == 0) {
        s_bmb = bm_b[0];
        float corr = 0.0f;
        #pragma unroll
        for (int o = 0; o < 20; o++) corr += bm_w[o] * fmaxf(h_b[o], 0.0f);
        s_corr = corr;
    }
    __syncthreads();

    // ---------------- per-thread: (batch PAIR g) x (output phase i) ----------------
    const int g = tid >> 3;
    const int i = tid & 7;
    const int bp = blockIdx.x * 16 + g;
    const int b0 = 2 * bp, b1 = b0 + 1;
    const bool valid0 = (b0 < B), valid1 = (b1 < B);
    const float* st0 = states + (valid0 ? b0 : 0) * 13;
    const float* st1 = states + (valid1 ? b1 : 0) * 13;

    const int a0 = (int)st0[0], a1 = (int)st1[0];
    const int p00 = s_pp[a0 * 2], p01 = s_pp[a0 * 2 + 1];
    const int p10 = s_pp[a1 * 2], p11 = s_pp[a1 * 2 + 1];
    const int mA = s_pp[i * 2], mB = s_pp[i * 2 + 1];

    // ---------- stage 0: pairs[i] = lane[mA] + lane[mB], packed (x=b0, y=b1) ----------
    ull pairs[16];
    #pragma unroll
    for (int c = 0; c < 16; c++) pairs[c] = 0ULL;

    #pragma unroll
    for (int t = 0; t < 2; t++) {
        const int m = (t == 0) ? mA : mB;
        const ull dm = f2pack(st0[1 + m], st1[1 + m]);
        ull de[4];
        #pragma unroll
        for (int k = 0; k < 4; k++) {
            float x, y; f2unpack(f2fma(dm, s_dw[k], s_db[k]), x, y);
            de[k] = f2pack(sigm(x), sigm(y));
        }
        const int e0 = (m == p00 || m == p01) ? 1 : 0;
        const int e1 = (m == p10 || m == p11) ? 1 : 0;
        #pragma unroll
        for (int c = 0; c < 16; c++) {
            ull acc = f2pack(s_base[e0][c], s_base[e1][c]);
            #pragma unroll
            for (int k = 0; k < 4; k++) acc = f2fma(de[k], s_leD[k][c], acc);
            pairs[c] = f2add(pairs[c], f2relu(acc));
        }
    }

    // ---------- stage 1: u = lcA@pairs + lc_b (REGS); v = lcB@pairs -> shared ----------
    ull u[20];
    const int vslot = g * SG + i * SI;
    #pragma unroll 2
    for (int o = 0; o < 20; o++) {
        const ulonglong2* wa = reinterpret_cast<const ulonglong2*>(&s_lcA[o][0]);
        const ulonglong2* wb = reinterpret_cast<const ulonglong2*>(&s_lcB[o][0]);
        ull au = s_lcb[o], av = 0ULL;
        #pragma unroll
        for (int cp = 0; cp < 8; cp++) {
            ulonglong2 A = wa[cp], Bv = wb[cp];
            au = f2fma(A.x,  pairs[cp * 2 + 0], au);
            av = f2fma(Bv.x, pairs[cp * 2 + 0], av);
            au = f2fma(A.y,  pairs[cp * 2 + 1], au);
            av = f2fma(Bv.y, pairs[cp * 2 + 1], av);
        }
        u[o] = au;
        s_v[vslot + o] = av;
    }
    __syncthreads();

    // ---------- stage 2: uniform 8-q loop (dummy q==i corrected via s_corr) ----------
    const int gv = g * SG;
    ull acc = 0ULL;

    #pragma unroll 1
    for (int q = 0; q < 8; q++) {
        const ulonglong2* vj = reinterpret_cast<const ulonglong2*>(&s_v[gv + q * SI]);
        const ulonglong2* rl = reinterpret_cast<const ulonglong2*>(&s_rel[(q * 8 + i) * SI]);

        ull comb[20];
        #pragma unroll
        for (int cp = 0; cp < 10; cp++) {
            ulonglong2 vv = vj[cp], rr = rl[cp];
            comb[cp * 2 + 0] = f2mul(f2relu(f2add(u[cp * 2 + 0], vv.x)), rr.x);
            comb[cp * 2 + 1] = f2mul(f2relu(f2add(u[cp * 2 + 1], vv.y)), rr.y);
        }

        #pragma unroll 2
        for (int o = 0; o < 20; o++) {
            const ulonglong2* hw2 = reinterpret_cast<const ulonglong2*>(&s_hw[o][0]);
            ull h = s_hb[o];
            #pragma unroll
            for (int cp = 0; cp < 10; cp++) {
                ulonglong2 w = hw2[cp];
                h = f2fma(w.x, comb[cp * 2 + 0], h);
                h = f2fma(w.y, comb[cp * 2 + 1], h);
            }
            acc = f2fma(s_bmw[o], f2relu(h), acc);
        }
    }

    float ax, ay; f2unpack(acc, ax, ay);
    const float fin = 7.0f * s_bmb - s_corr;
    if (valid0) out[b0 * 8 + i] = ax + fin;
    if (valid1) out[b1 * 8 + i] = ay + fin;
}

extern "C" void kernel_launch(void* const* d_in, const int* in_sizes, int n_in,
                              void* d_out, int out_size)
{
    const float* states      = (const float*)d_in[0];
    const int*   comp_mask   = (const int*)  d_in[1];
    const int*   phase_pairs = (const int*)  d_in[2];
    const float* p_w  = (const float*)d_in[3];
    const float* d_w  = (const float*)d_in[4];
    const float* d_b  = (const float*)d_in[5];
    const float* le_w = (const float*)d_in[6];
    const float* le_b = (const float*)d_in[7];
    const float* lc_w = (const float*)d_in[8];
    const float* lc_b = (const float*)d_in[9];
    const float* rel_w = (const float*)d_in[10];
    const float* rc_w  = (const float*)d_in[11];
    const float* rc_b  = (const float*)d_in[12];
    const float* h_w   = (const float*)d_in[13];
    const float* h_b   = (const float*)d_in[14];
    const float* bm_w  = (const float*)d_in[15];
    const float* bm_b  = (const float*)d_in[16];

    const int B = in_sizes[0] / 13;           // states is [B, 1 + 12]
    const int blocks = (B + 31) / 32;         // 16 batch PAIRS (32 elems) per block

    frap_kernel<<<blocks, 128>>>(states, comp_mask, phase_pairs,
                                 p_w, d_w, d_b, le_w, le_b, lc_w, lc_b,
                                 rel_w, rc_w, rc_b, h_w, h_b, bm_w, bm_b,
                                 (float*)d_out, B);
}

// round 8
// speedup vs baseline: 1.1031x; 1.1031x over previous
#include <cuda_runtime.h>
#include <cstdint>

using ull = unsigned long long;

// ---------- packed f32x2 helpers (pack axis = channel c, NOT batch) ----------
__device__ __forceinline__ ull f2add(ull a, ull b) {
    ull d; asm("add.rn.f32x2 %0, %1, %2;" : "=l"(d) : "l"(a), "l"(b)); return d;
}
__device__ __forceinline__ ull f2mul(ull a, ull b) {
    ull d; asm("mul.rn.f32x2 %0, %1, %2;" : "=l"(d) : "l"(a), "l"(b)); return d;
}
__device__ __forceinline__ ull f2fma(ull a, ull b, ull c) {
    ull d; asm("fma.rn.f32x2 %0, %1, %2, %3;" : "=l"(d) : "l"(a), "l"(b), "l"(c)); return d;
}
// relu on both halves; movs coalesce into register-pair aliasing in SASS
__device__ __forceinline__ ull f2relu(ull p) {
    ull d;
    asm("{ .reg .f32 lo, hi;\n\t"
        "  mov.b64 {lo, hi}, %1;\n\t"
        "  max.f32 lo, lo, 0f00000000;\n\t"
        "  max.f32 hi, hi, 0f00000000;\n\t"
        "  mov.b64 %0, {lo, hi}; }" : "=l"(d) : "l"(p));
    return d;
}
__device__ __forceinline__ float f2hadd(ull p) {
    float a, b; asm("mov.b64 {%0, %1}, %2;" : "=f"(a), "=f"(b) : "l"(p));
    return a + b;
}
__device__ __forceinline__ ull f2pack(float a, float b) {
    ull r; asm("mov.b64 %0, {%1, %2};" : "=l"(r) : "f"(a), "f"(b)); return r;
}
__device__ __forceinline__ float sigm(float x) { return 1.0f / (1.0f + __expf(-x)); }

// u/v exchange layout (floats): addr = g*168 + phase*20 + c.
// 168 mod 32 = 8 -> 4 per-warp g-bases hit bank quads 0/8/16/24: LDS128 1 wavefront.
// rel rows at (q*8+i)*20: 20i mod 32 gives 8 distinct bank quads: 1 wavefront.
#define G_STRIDE 168

__global__ __launch_bounds__(128, 4)
void frap_kernel(const float* __restrict__ states,
                 const int*   __restrict__ comp_mask,
                 const int*   __restrict__ phase_pairs,
                 const float* __restrict__ p_w,
                 const float* __restrict__ d_w,  const float* __restrict__ d_b,
                 const float* __restrict__ le_w, const float* __restrict__ le_b,
                 const float* __restrict__ lc_w, const float* __restrict__ lc_b,
                 const float* __restrict__ rel_w,
                 const float* __restrict__ rc_w, const float* __restrict__ rc_b,
                 const float* __restrict__ h_w,  const float* __restrict__ h_b,
                 const float* __restrict__ bm_w, const float* __restrict__ bm_b,
                 float* __restrict__ out, int B)
{
    __shared__ __align__(16) float s_lcA[20][16];     // lc_w[:, 0:16]
    __shared__ __align__(16) float s_lcB[20][16];     // lc_w[:, 16:32]
    __shared__ __align__(16) float s_hw[20][20];      // scalar rows: natural c-pairs for f32x2
    __shared__ __align__(16) float s_rel[8 * 8 * 20]; // [q][i][20]; zero row when q==i
    __shared__ float s_leD[4][16];
    __shared__ float s_lcb[20], s_bmw[20], s_dw[4], s_db[4];
    __shared__ ull   s_hb2[20];                       // packed (h_b[o], 0)
    __shared__ float s_base[2][16];
    __shared__ int   s_pp[16];
    __shared__ float s_bmb, s_corr;                   // corr = sum_o bm[o]*relu(h_b[o])
    __shared__ __align__(16) float s_u[16 * G_STRIDE];
    __shared__ __align__(16) float s_v[16 * G_STRIDE];

    const int tid = threadIdx.x;

    // ---------------- block-local precompute ----------------
    for (int idx = tid; idx < 320; idx += 128) {
        int o = idx >> 4, c = idx & 15;
        s_lcA[o][c] = lc_w[o * 32 + c];
        s_lcB[o][c] = lc_w[o * 32 + 16 + c];
    }
    for (int idx = tid; idx < 400; idx += 128) {
        int o = idx / 20, c = idx % 20;
        s_hw[o][c] = h_w[o * 20 + c];
    }
    // s_rel[q][i][o]: rel row for pair (i, j=q); zero when q==i (dummy lane, corrected)
    for (int idx = tid; idx < 1280; idx += 128) {
        int qi = idx / 20, o = idx % 20;
        int q = qi >> 3, i = qi & 7;
        float val = 0.0f;
        if (q != i) {
            int cm = i * 7 + (q > i ? q - 1 : q);
            int e = comp_mask[cm];
            float acc = rc_b[o];
            #pragma unroll
            for (int c4 = 0; c4 < 4; c4++)
                acc += fmaxf(rel_w[e * 4 + c4], 0.0f) * rc_w[o * 4 + c4];
            val = fmaxf(acc, 0.0f);
        }
        s_rel[qi * 20 + o] = val;
    }
    for (int idx = tid; idx < 64; idx += 128) {
        int k = idx >> 4, c = idx & 15;
        s_leD[k][c] = le_w[(4 + k) * 16 + c];
    }
    if (tid < 32) {
        int e = tid >> 4, c = tid & 15;
        float a = le_b[c];
        #pragma unroll
        for (int k = 0; k < 4; k++) a += sigm(p_w[e * 4 + k]) * le_w[k * 16 + c];
        s_base[e][c] = a;
    }
    if (tid < 20) {
        s_lcb[tid] = lc_b[tid];
        s_bmw[tid] = bm_w[tid];
        s_hb2[tid] = f2pack(h_b[tid], 0.0f);
    }
    if (tid < 4) { s_dw[tid] = d_w[tid]; s_db[tid] = d_b[tid]; }
    if (tid < 16) s_pp[tid] = phase_pairs[tid];
    if (tid == 0) {
        s_bmb = bm_b[0];
        float corr = 0.0f;
        #pragma unroll
        for (int o = 0; o < 20; o++) corr += bm_w[o] * fmaxf(h_b[o], 0.0f);
        s_corr = corr;
    }
    __syncthreads();

    // ---------------- per-thread: (batch elem b) x (output phase i) ----------------
    const int g = tid >> 3;
    const int i = tid & 7;
    const int b = blockIdx.x * 16 + g;
    const bool valid = (b < B);
    const float* st = states + (valid ? b : 0) * 13;

    const int a  = (int)st[0];
    const int pa0 = s_pp[a * 2], pa1 = s_pp[a * 2 + 1];
    const int mA  = s_pp[i * 2], mB  = s_pp[i * 2 + 1];

    // ---------- stage 0: pairs[i] = lane[mA] + lane[mB] ----------
    float pairs[16];
    #pragma unroll
    for (int c = 0; c < 16; c++) pairs[c] = 0.0f;

    #pragma unroll
    for (int t = 0; t < 2; t++) {
        const int m = (t == 0) ? mA : mB;
        const float dm = st[1 + m];
        float de[4];
        #pragma unroll
        for (int k = 0; k < 4; k++) de[k] = sigm(fmaf(dm, s_dw[k], s_db[k]));
        const int e = (m == pa0 || m == pa1) ? 1 : 0;
        #pragma unroll
        for (int c = 0; c < 16; c++) {
            float acc = s_base[e][c];
            #pragma unroll
            for (int k = 0; k < 4; k++) acc = fmaf(de[k], s_leD[k][c], acc);
            pairs[c] += fmaxf(acc, 0.0f);
        }
    }

    // ---------- stage 1: u = lcA@pairs + lc_b; v = lcB@pairs -> shared ----------
    const int slot = g * G_STRIDE + i * 20;
    {
        float4* u4p = reinterpret_cast<float4*>(&s_u[slot]);
        float4* v4p = reinterpret_cast<float4*>(&s_v[slot]);
        #pragma unroll 1
        for (int ob = 0; ob < 5; ob++) {
            float ur[4], vr[4];
            #pragma unroll
            for (int oi = 0; oi < 4; oi++) {
                const int o = ob * 4 + oi;
                const float4* wa = reinterpret_cast<const float4*>(&s_lcA[o][0]);
                const float4* wb = reinterpret_cast<const float4*>(&s_lcB[o][0]);
                float au = s_lcb[o], av = 0.0f;
                #pragma unroll
                for (int c4 = 0; c4 < 4; c4++) {
                    float4 A = wa[c4], Bv = wb[c4];
                    au = fmaf(A.x,  pairs[c4 * 4 + 0], au);
                    av = fmaf(Bv.x, pairs[c4 * 4 + 0], av);
                    au = fmaf(A.y,  pairs[c4 * 4 + 1], au);
                    av = fmaf(Bv.y, pairs[c4 * 4 + 1], av);
                    au = fmaf(A.z,  pairs[c4 * 4 + 2], au);
                    av = fmaf(Bv.z, pairs[c4 * 4 + 2], av);
                    au = fmaf(A.w,  pairs[c4 * 4 + 3], au);
                    av = fmaf(Bv.w, pairs[c4 * 4 + 3], av);
                }
                ur[oi] = au; vr[oi] = av;
            }
            u4p[ob] = make_float4(ur[0], ur[1], ur[2], ur[3]);
            v4p[ob] = make_float4(vr[0], vr[1], vr[2], vr[3]);
        }
    }
    __syncthreads();

    // ---------- stage 2: packed-by-c f32x2, q chunked by 2 ----------
    // u as 10 natural c-pairs (direct reinterpret, zero packing instructions)
    ull up[10];
    {
        const ulonglong2* uu = reinterpret_cast<const ulonglong2*>(&s_u[slot]);
        #pragma unroll
        for (int k = 0; k < 5; k++) { ulonglong2 t = uu[k]; up[2*k] = t.x; up[2*k+1] = t.y; }
    }

    const int gv = g * G_STRIDE;
    float acc = 0.0f;

    #pragma unroll 1
    for (int qc = 0; qc < 4; qc++) {
        const int q0 = 2 * qc, q1 = q0 + 1;
        ull c0[10], c1[10];
        {
            const ulonglong2* v0 = reinterpret_cast<const ulonglong2*>(&s_v[gv + q0 * 20]);
            const ulonglong2* r0 = reinterpret_cast<const ulonglong2*>(&s_rel[(q0 * 8 + i) * 20]);
            const ulonglong2* v1 = reinterpret_cast<const ulonglong2*>(&s_v[gv + q1 * 20]);
            const ulonglong2* r1 = reinterpret_cast<const ulonglong2*>(&s_rel[(q1 * 8 + i) * 20]);
            #pragma unroll
            for (int k = 0; k < 5; k++) {
                ulonglong2 va = v0[k], ra = r0[k];
                ulonglong2 vb = v1[k], rb = r1[k];
                c0[2*k+0] = f2mul(f2relu(f2add(up[2*k+0], va.x)), ra.x);
                c0[2*k+1] = f2mul(f2relu(f2add(up[2*k+1], va.y)), ra.y);
                c1[2*k+0] = f2mul(f2relu(f2add(up[2*k+0], vb.x)), rb.x);
                c1[2*k+1] = f2mul(f2relu(f2add(up[2*k+1], vb.y)), rb.y);
            }
        }

        #pragma unroll 2
        for (int o = 0; o < 20; o++) {
            const ulonglong2* w2 = reinterpret_cast<const ulonglong2*>(&s_hw[o][0]);
            ull h0 = s_hb2[o], h1 = h0;     // (h_b, 0) packed
            #pragma unroll
            for (int k = 0; k < 5; k++) {
                ulonglong2 w = w2[k];       // two natural weight c-pairs
                h0 = f2fma(w.x, c0[2*k+0], h0);
                h1 = f2fma(w.x, c1[2*k+0], h1);
                h0 = f2fma(w.y, c0[2*k+1], h0);
                h1 = f2fma(w.y, c1[2*k+1], h1);
            }
            const float bw = s_bmw[o];
            acc = fmaf(bw, fmaxf(f2hadd(h0), 0.0f), acc);
            acc = fmaf(bw, fmaxf(f2hadd(h1), 0.0f), acc);
        }
    }

    // subtract dummy-q contribution (comb=0 -> h=h_b), add 7x bm bias
    if (valid) out[b * 8 + i] = acc - s_corr + 7.0f * s_bmb;
}

extern "C" void kernel_launch(void* const* d_in, const int* in_sizes, int n_in,
                              void* d_out, int out_size)
{
    const float* states      = (const float*)d_in[0];
    const int*   comp_mask   = (const int*)  d_in[1];
    const int*   phase_pairs = (const int*)  d_in[2];
    const float* p_w  = (const float*)d_in[3];
    const float* d_w  = (const float*)d_in[4];
    const float* d_b  = (const float*)d_in[5];
    const float* le_w = (const float*)d_in[6];
    const float* le_b = (const float*)d_in[7];
    const float* lc_w = (const float*)d_in[8];
    const float* lc_b = (const float*)d_in[9];
    const float* rel_w = (const float*)d_in[10];
    const float* rc_w  = (const float*)d_in[11];
    const float* rc_b  = (const float*)d_in[12];
    const float* h_w   = (const float*)d_in[13];
    const float* h_b   = (const float*)d_in[14];
    const float* bm_w  = (const float*)d_in[15];
    const float* bm_b  = (const float*)d_in[16];

    const int B = in_sizes[0] / 13;           // states is [B, 1 + 12]
    const int blocks = (B + 15) / 16;         // 16 batch elems x 8 phases per 128-thread block

    frap_kernel<<<blocks, 128>>>(states, comp_mask, phase_pairs,
                                 p_w, d_w, d_b, le_w, le_b, lc_w, lc_b,
                                 rel_w, rc_w, rc_b, h_w, h_b, bm_w, bm_b,
                                 (float*)d_out, B);
}

// round 9
// speedup vs baseline: 1.1870x; 1.0761x over previous
#include <cuda_runtime.h>
#include <cstdint>

using ull = unsigned long long;

// ---------- packed f32x2 helpers (pack axis = channel c) ----------
__device__ __forceinline__ ull f2add(ull a, ull b) {
    ull d; asm("add.rn.f32x2 %0, %1, %2;" : "=l"(d) : "l"(a), "l"(b)); return d;
}
__device__ __forceinline__ ull f2mul(ull a, ull b) {
    ull d; asm("mul.rn.f32x2 %0, %1, %2;" : "=l"(d) : "l"(a), "l"(b)); return d;
}
__device__ __forceinline__ ull f2fma(ull a, ull b, ull c) {
    ull d; asm("fma.rn.f32x2 %0, %1, %2, %3;" : "=l"(d) : "l"(a), "l"(b), "l"(c)); return d;
}
__device__ __forceinline__ ull f2relu(ull p) {
    ull d;
    asm("{ .reg .f32 lo, hi;\n\t"
        "  mov.b64 {lo, hi}, %1;\n\t"
        "  max.f32 lo, lo, 0f00000000;\n\t"
        "  max.f32 hi, hi, 0f00000000;\n\t"
        "  mov.b64 %0, {lo, hi}; }" : "=l"(d) : "l"(p));
    return d;
}
__device__ __forceinline__ float f2hadd(ull p) {
    float a, b; asm("mov.b64 {%0, %1}, %2;" : "=f"(a), "=f"(b) : "l"(p));
    return a + b;
}
__device__ __forceinline__ ull f2pack(float a, float b) {
    ull r; asm("mov.b64 %0, {%1, %2};" : "=l"(r) : "f"(a), "f"(b)); return r;
}
__device__ __forceinline__ float sigm(float x) { return 1.0f / (1.0f + __expf(-x)); }

// u/v exchange layout (floats): addr = g*168 + phase*20 + c.
// 168 mod 32 = 8 -> 4 per-warp g-bases hit bank quads 0/8/16/24: LDS128 1 wavefront.
#define G_STRIDE 168

__global__ __launch_bounds__(128, 4)
void frap_kernel(const float* __restrict__ states,
                 const int*   __restrict__ comp_mask,
                 const int*   __restrict__ phase_pairs,
                 const float* __restrict__ p_w,
                 const float* __restrict__ d_w,  const float* __restrict__ d_b,
                 const float* __restrict__ le_w, const float* __restrict__ le_b,
                 const float* __restrict__ lc_w, const float* __restrict__ lc_b,
                 const float* __restrict__ rel_w,
                 const float* __restrict__ rc_w, const float* __restrict__ rc_b,
                 const float* __restrict__ h_w,  const float* __restrict__ h_b,
                 const float* __restrict__ bm_w, const float* __restrict__ bm_b,
                 float* __restrict__ out, int B)
{
    __shared__ __align__(16) float s_lcA[20][16];     // lc_w[:, 0:16]
    __shared__ __align__(16) float s_lcB[20][16];     // lc_w[:, 16:32]
    __shared__ __align__(16) float s_hw[20][20];      // natural c-pairs for f32x2
    __shared__ __align__(16) float s_rel[8 * 8 * 20]; // [q][i][20]; zero row when q==i
    __shared__ float s_leD[4][16];
    __shared__ float s_lcb[20], s_bmw[20], s_dw[4], s_db[4];
    __shared__ ull   s_hb2[20];                       // packed (h_b[o], 0)
    __shared__ float s_base[2][16];
    __shared__ int   s_pp[16];
    __shared__ float s_bmb, s_corr;                   // corr = sum_o bm[o]*relu(h_b[o])
    __shared__ __align__(16) float s_u[16 * G_STRIDE];
    __shared__ __align__(16) float s_v[16 * G_STRIDE];

    const int tid = threadIdx.x;

    // ---------------- block-local precompute ----------------
    for (int idx = tid; idx < 320; idx += 128) {
        int o = idx >> 4, c = idx & 15;
        s_lcA[o][c] = lc_w[o * 32 + c];
        s_lcB[o][c] = lc_w[o * 32 + 16 + c];
    }
    for (int idx = tid; idx < 400; idx += 128) {
        int o = idx / 20, c = idx % 20;
        s_hw[o][c] = h_w[o * 20 + c];
    }
    // s_rel[q][i][o]: rel row for pair (i, j=q); zero when q==i (dummy lane, corrected)
    for (int idx = tid; idx < 1280; idx += 128) {
        int qi = idx / 20, o = idx % 20;
        int q = qi >> 3, i = qi & 7;
        float val = 0.0f;
        if (q != i) {
            int cm = i * 7 + (q > i ? q - 1 : q);
            int e = comp_mask[cm];
            float acc = rc_b[o];
            #pragma unroll
            for (int c4 = 0; c4 < 4; c4++)
                acc += fmaxf(rel_w[e * 4 + c4], 0.0f) * rc_w[o * 4 + c4];
            val = fmaxf(acc, 0.0f);
        }
        s_rel[qi * 20 + o] = val;
    }
    for (int idx = tid; idx < 64; idx += 128) {
        int k = idx >> 4, c = idx & 15;
        s_leD[k][c] = le_w[(4 + k) * 16 + c];
    }
    if (tid < 32) {
        int e = tid >> 4, c = tid & 15;
        float a = le_b[c];
        #pragma unroll
        for (int k = 0; k < 4; k++) a += sigm(p_w[e * 4 + k]) * le_w[k * 16 + c];
        s_base[e][c] = a;
    }
    if (tid < 20) {
        s_lcb[tid] = lc_b[tid];
        s_bmw[tid] = bm_w[tid];
        s_hb2[tid] = f2pack(h_b[tid], 0.0f);
    }
    if (tid < 4) { s_dw[tid] = d_w[tid]; s_db[tid] = d_b[tid]; }
    if (tid < 16) s_pp[tid] = phase_pairs[tid];
    if (tid == 0) {
        s_bmb = bm_b[0];
        float corr = 0.0f;
        #pragma unroll
        for (int o = 0; o < 20; o++) corr += bm_w[o] * fmaxf(h_b[o], 0.0f);
        s_corr = corr;
    }
    __syncthreads();

    // ---------------- per-thread: (batch elem b) x (output phase i) ----------------
    const int g = tid >> 3;
    const int i = tid & 7;
    const int b = blockIdx.x * 16 + g;
    const bool valid = (b < B);
    const float* st = states + (valid ? b : 0) * 13;

    const int a  = (int)st[0];
    const int pa0 = s_pp[a * 2], pa1 = s_pp[a * 2 + 1];
    const int mA  = s_pp[i * 2], mB  = s_pp[i * 2 + 1];

    // ---------- stage 0: pairs[i] = lane[mA] + lane[mB] ----------
    float pairs[16];
    #pragma unroll
    for (int c = 0; c < 16; c++) pairs[c] = 0.0f;

    #pragma unroll
    for (int t = 0; t < 2; t++) {
        const int m = (t == 0) ? mA : mB;
        const float dm = st[1 + m];
        float de[4];
        #pragma unroll
        for (int k = 0; k < 4; k++) de[k] = sigm(fmaf(dm, s_dw[k], s_db[k]));
        const int e = (m == pa0 || m == pa1) ? 1 : 0;
        #pragma unroll
        for (int c = 0; c < 16; c++) {
            float acc = s_base[e][c];
            #pragma unroll
            for (int k = 0; k < 4; k++) acc = fmaf(de[k], s_leD[k][c], acc);
            pairs[c] += fmaxf(acc, 0.0f);
        }
    }

    // ---------- stage 1: u = lcA@pairs + lc_b; v = lcB@pairs -> shared ----------
    const int slot = g * G_STRIDE + i * 20;
    {
        float4* u4p = reinterpret_cast<float4*>(&s_u[slot]);
        float4* v4p = reinterpret_cast<float4*>(&s_v[slot]);
        #pragma unroll 1
        for (int ob = 0; ob < 5; ob++) {
            float ur[4], vr[4];
            #pragma unroll
            for (int oi = 0; oi < 4; oi++) {
                const int o = ob * 4 + oi;
                const float4* wa = reinterpret_cast<const float4*>(&s_lcA[o][0]);
                const float4* wb = reinterpret_cast<const float4*>(&s_lcB[o][0]);
                float au = s_lcb[o], av = 0.0f;
                #pragma unroll
                for (int c4 = 0; c4 < 4; c4++) {
                    float4 A = wa[c4], Bv = wb[c4];
                    au = fmaf(A.x,  pairs[c4 * 4 + 0], au);
                    av = fmaf(Bv.x, pairs[c4 * 4 + 0], av);
                    au = fmaf(A.y,  pairs[c4 * 4 + 1], au);
                    av = fmaf(Bv.y, pairs[c4 * 4 + 1], av);
                    au = fmaf(A.z,  pairs[c4 * 4 + 2], au);
                    av = fmaf(Bv.z, pairs[c4 * 4 + 2], av);
                    au = fmaf(A.w,  pairs[c4 * 4 + 3], au);
                    av = fmaf(Bv.w, pairs[c4 * 4 + 3], av);
                }
                ur[oi] = au; vr[oi] = av;
            }
            u4p[ob] = make_float4(ur[0], ur[1], ur[2], ur[3]);
            v4p[ob] = make_float4(vr[0], vr[1], vr[2], vr[3]);
        }
    }
    __syncthreads();

    // ---------- stage 2: packed-by-c f32x2, q chunked by 4 (weights amortized 4x) ----------
    const int gv = g * G_STRIDE;
    float acc = 0.0f;

    #pragma unroll 1
    for (int qc = 0; qc < 2; qc++) {
        const int qb = qc * 4;
        ull cb[4][10];
        {
            // u reloaded per chunk (frees 20 persistent regs; costs 5 LDS128 x2 chunks)
            ull up[10];
            const ulonglong2* uu = reinterpret_cast<const ulonglong2*>(&s_u[slot]);
            #pragma unroll
            for (int k = 0; k < 5; k++) { ulonglong2 t = uu[k]; up[2*k] = t.x; up[2*k+1] = t.y; }

            #pragma unroll
            for (int qq = 0; qq < 4; qq++) {
                const int q = qb + qq;
                const ulonglong2* vq = reinterpret_cast<const ulonglong2*>(&s_v[gv + q * 20]);
                const ulonglong2* rq = reinterpret_cast<const ulonglong2*>(&s_rel[(q * 8 + i) * 20]);
                #pragma unroll
                for (int k = 0; k < 5; k++) {
                    ulonglong2 vv = vq[k], rr = rq[k];
                    cb[qq][2*k+0] = f2mul(f2relu(f2add(up[2*k+0], vv.x)), rr.x);
                    cb[qq][2*k+1] = f2mul(f2relu(f2add(up[2*k+1], vv.y)), rr.y);
                }
            }
        }

        #pragma unroll 1
        for (int o = 0; o < 20; o++) {
            const ulonglong2* w2 = reinterpret_cast<const ulonglong2*>(&s_hw[o][0]);
            ull h0 = s_hb2[o], h1 = h0, h2 = h0, h3 = h0;   // 4 independent chains (ILP)
            #pragma unroll
            for (int k = 0; k < 5; k++) {
                ulonglong2 w = w2[k];
                h0 = f2fma(w.x, cb[0][2*k+0], h0);
                h1 = f2fma(w.x, cb[1][2*k+0], h1);
                h2 = f2fma(w.x, cb[2][2*k+0], h2);
                h3 = f2fma(w.x, cb[3][2*k+0], h3);
                h0 = f2fma(w.y, cb[0][2*k+1], h0);
                h1 = f2fma(w.y, cb[1][2*k+1], h1);
                h2 = f2fma(w.y, cb[2][2*k+1], h2);
                h3 = f2fma(w.y, cb[3][2*k+1], h3);
            }
            const float bw = s_bmw[o];
            acc = fmaf(bw, fmaxf(f2hadd(h0), 0.0f), acc);
            acc = fmaf(bw, fmaxf(f2hadd(h1), 0.0f), acc);
            acc = fmaf(bw, fmaxf(f2hadd(h2), 0.0f), acc);
            acc = fmaf(bw, fmaxf(f2hadd(h3), 0.0f), acc);
        }
    }

    // subtract dummy-q contribution (comb=0 -> h=h_b), add 7x bm bias
    if (valid) out[b * 8 + i] = acc - s_corr + 7.0f * s_bmb;
}

extern "C" void kernel_launch(void* const* d_in, const int* in_sizes, int n_in,
                              void* d_out, int out_size)
{
    const float* states      = (const float*)d_in[0];
    const int*   comp_mask   = (const int*)  d_in[1];
    const int*   phase_pairs = (const int*)  d_in[2];
    const float* p_w  = (const float*)d_in[3];
    const float* d_w  = (const float*)d_in[4];
    const float* d_b  = (const float*)d_in[5];
    const float* le_w = (const float*)d_in[6];
    const float* le_b = (const float*)d_in[7];
    const float* lc_w = (const float*)d_in[8];
    const float* lc_b = (const float*)d_in[9];
    const float* rel_w = (const float*)d_in[10];
    const float* rc_w  = (const float*)d_in[11];
    const float* rc_b  = (const float*)d_in[12];
    const float* h_w   = (const float*)d_in[13];
    const float* h_b   = (const float*)d_in[14];
    const float* bm_w  = (const float*)d_in[15];
    const float* bm_b  = (const float*)d_in[16];

    const int B = in_sizes[0] / 13;           // states is [B, 1 + 12]
    const int blocks = (B + 15) / 16;         // 16 batch elems x 8 phases per 128-thread block

    frap_kernel<<<blocks, 128>>>(states, comp_mask, phase_pairs,
                                 p_w, d_w, d_b, le_w, le_b, lc_w, lc_b,
                                 rel_w, rc_w, rc_b, h_w, h_b, bm_w, bm_b,
                                 (float*)d_out, B);
}